// round 11
// baseline (speedup 1.0000x reference)
#include <cuda_runtime.h>
#include <cstdint>

#define BSZ    256
#define BOND   5
#define NDIM   128
#define ATOM   64
#define UNITS  128
#define THREADS 128
#define MHALF  64    // M rows per CTA (sample split in half)

// smem float-word pitches (conflict-free fragment access; pitch % 32 == 4 or 8)
#define P_F    72    // F    [n=128][d=64]   (pre-rounded tf32 at staging)
#define P_AW   36    // adjW [m=64][n=32]    2 rotating window buffers
#define P_K    136   // K    [d=64][u=128]   single buffer
#define P_X1   68    // X1   [m=64][d=64]

// smem layout in float words: F | adjW0 | adjW1 | K | X1
#define OFF_F    0
#define OFF_AW   (OFF_F  + NDIM * P_F)       // 9216
#define OFF_K    (OFF_AW + 2 * MHALF * P_AW) // 13824
#define OFF_X1   (OFF_K  + ATOM * P_K)       // 22528
#define SMEM_WORDS (OFF_X1 + MHALF * P_X1)   // 26880
#define SMEM_BYTES (SMEM_WORDS * 4)          // 107520 (x2 CTAs = 215040 <= 228KB)

__device__ __forceinline__ float f2tf32f(float f) {
    uint32_t u;
    asm("cvt.rna.tf32.f32 %0, %1;" : "=r"(u) : "f"(f));
    return __uint_as_float(u);
}

__device__ __forceinline__ void mma_tf32(float c[4], const uint32_t a[4], const uint32_t b[2]) {
    asm volatile(
        "mma.sync.aligned.m16n8k8.row.col.f32.tf32.tf32.f32 "
        "{%0,%1,%2,%3}, {%4,%5,%6,%7}, {%8,%9}, {%0,%1,%2,%3};"
        : "+f"(c[0]), "+f"(c[1]), "+f"(c[2]), "+f"(c[3])
        : "r"(a[0]), "r"(a[1]), "r"(a[2]), "r"(a[3]), "r"(b[0]), "r"(b[1]));
}

__device__ __forceinline__ uint32_t smem_u32(const void* p) {
    uint32_t a;
    asm("{ .reg .u64 t; cvta.to.shared.u64 t, %1; cvt.u32.u64 %0, t; }" : "=r"(a) : "l"(p));
    return a;
}
__device__ __forceinline__ void cpa16(uint32_t s, const float4* g) {
    asm volatile("cp.async.cg.shared.global [%0], [%1], 16;" :: "r"(s), "l"(g) : "memory");
}
#define CP_COMMIT() asm volatile("cp.async.commit_group;" ::: "memory")
template<int N> __device__ __forceinline__ void cp_wait() {
    asm volatile("cp.async.wait_group %0;" :: "n"(N) : "memory");
}

__global__ void __launch_bounds__(THREADS, 2)
rgc_kernel(const float* __restrict__ adjacency,
           const float* __restrict__ features,
           const float* __restrict__ kern,
           float* __restrict__ out) {
    extern __shared__ float sm[];
    float* sF   = sm + OFF_F;
    float* sAW  = sm + OFF_AW;    // 2 bufs of MHALF*P_AW
    float* sK   = sm + OFF_K;
    float* sX1  = sm + OFF_X1;

    const uint32_t smb  = smem_u32(sm);
    const uint32_t sAWB = smb + OFF_AW * 4u;
    const uint32_t sKB  = smb + OFF_K * 4u;

    const int tid = threadIdx.x;
    const int wid = tid >> 5;
    const int lid = tid & 31;
    const int r4  = lid >> 2;
    const int c4  = lid & 3;
    const int b   = blockIdx.x >> 1;
    const int mh  = (blockIdx.x & 1) << 6;   // 0 or 64

    // 4 warps, R5-shaped tiles: G1 32m x 32d, G2 32m x 64u
    const int m0 = (wid & 1) * 32;
    const int d0 = (wid >> 1) * 32;
    const int u0 = (wid >> 1) * 64;

    const float4* adjB  = reinterpret_cast<const float4*>(adjacency) + (size_t)(b * BOND) * 4096;
    const float4* kerB  = reinterpret_cast<const float4*>(kern)      + (size_t)(b * BOND) * 2048;
    const float4* featB = reinterpret_cast<const float4*>(features)  + (size_t)b * 2048;

    // stage adj chunk c of bond e (rows mh..mh+63, cols c*32..+32) -> window buf c&1
    auto stage_chunk = [&](int e, int c) {
        const float4* src = adjB + (size_t)e * 4096;
        uint32_t dst = sAWB + (uint32_t)((c & 1) * MHALF * P_AW) * 4u;
        #pragma unroll
        for (int t = 0; t < 4; t++) {
            int i = tid + t * THREADS;          // 0..511
            int m = i >> 3, j = i & 7;
            cpa16(dst + (uint32_t)(m * P_AW + j * 4) * 4u,
                  src + (mh + m) * 32 + c * 8 + j);
        }
    };
    auto stage_K = [&](int e) {
        const float4* src = kerB + (size_t)e * 2048;
        #pragma unroll
        for (int t = 0; t < 16; t++) {
            int i = tid + t * THREADS;          // 0..2047
            int dd = i >> 5, u4 = i & 31;
            cpa16(sKB + (uint32_t)(dd * P_K + u4 * 4) * 4u, src + i);
        }
    };

    // ---- prologue: F (LDG+cvt+STS, pre-rounded), then C0(0), C1(0) ----
    {
        #pragma unroll
        for (int t = 0; t < 16; t++) {
            int i = tid + t * THREADS;          // 0..2047
            float4 v = featB[i];
            int node = i >> 4, a4 = i & 15;
            float* d = sF + node * P_F + a4 * 4;
            d[0] = f2tf32f(v.x); d[1] = f2tf32f(v.y);
            d[2] = f2tf32f(v.z); d[3] = f2tf32f(v.w);
        }
        stage_chunk(0, 0); CP_COMMIT();
        stage_chunk(0, 1); CP_COMMIT();
    }

    float acc2[2][8][4];
    #pragma unroll
    for (int mt = 0; mt < 2; mt++)
        #pragma unroll
        for (int nt = 0; nt < 8; nt++)
            #pragma unroll
            for (int k = 0; k < 4; k++) acc2[mt][nt][k] = 0.0f;

    float acc1[2][4][4];
    // GEMM1 over one 32-col window buf; global n-base = c*32
    auto g1_chunk = [&](int c) {
        const float* sC = sAW + (c & 1) * MHALF * P_AW;
        #pragma unroll
        for (int ks = 0; ks < 4; ks++) {
            const int kk = ks * 8;
            uint32_t a[2][4];
            #pragma unroll
            for (int mt = 0; mt < 2; mt++) {
                const float* pa = sC + (m0 + mt * 16 + r4) * P_AW + kk + c4;
                a[mt][0] = __float_as_uint(pa[0]);           // raw fp32 (HW tf32 trunc)
                a[mt][1] = __float_as_uint(pa[8 * P_AW]);
                a[mt][2] = __float_as_uint(pa[4]);
                a[mt][3] = __float_as_uint(pa[8 * P_AW + 4]);
            }
            uint32_t bf[4][2];
            #pragma unroll
            for (int nt = 0; nt < 4; nt++) {
                const float* pb = sF + (c * 32 + kk + c4) * P_F + d0 + nt * 8 + r4;
                bf[nt][0] = __float_as_uint(pb[0]);          // pre-rounded at staging
                bf[nt][1] = __float_as_uint(pb[4 * P_F]);
            }
            #pragma unroll
            for (int mt = 0; mt < 2; mt++)
                #pragma unroll
                for (int nt = 0; nt < 4; nt++)
                    mma_tf32(acc1[mt][nt], a[mt], bf[nt]);
        }
    };

    // Corrected FIFO (commit into a buffer only after the bar that closes its
    // previous consumer):
    //  entry flight: {C0,C1}
    //  s0: wait<1>|bar| commit{K}   | g1(0)@buf0      flight {C1,K}
    //  s1: wait<1>|bar| commit{C2}  | g1(1)@buf1      (C2->buf0: g1(0) closed)
    //  s2: wait<0>|bar| commit{C3}  | g1(2)@buf0      (C3->buf1: g1(1) closed; K landed)
    //  s3: wait<0>|bar| commit{C0'} | g1(3)@buf1      (C0'->buf0: g1(2) closed)
    //  X1store|bar| commit{C1'}                        (C1'->buf1: g1(3) closed)
    //  G2(e); next bond s0-bar closes G2 before K(e+1) commit
    #pragma unroll 1
    for (int e = 0; e < BOND; e++) {
        #pragma unroll
        for (int mt = 0; mt < 2; mt++)
            #pragma unroll
            for (int nt = 0; nt < 4; nt++)
                #pragma unroll
                for (int k = 0; k < 4; k++) acc1[mt][nt][k] = 0.0f;

        cp_wait<1>(); __syncthreads();          // C0(e) ready; G2(e-1) closed
        stage_K(e); CP_COMMIT();
        g1_chunk(0);

        cp_wait<1>(); __syncthreads();          // C1(e) ready; g1(0) closed
        stage_chunk(e, 2); CP_COMMIT();
        g1_chunk(1);

        cp_wait<0>(); __syncthreads();          // K(e), C2(e) ready; g1(1) closed
        stage_chunk(e, 3); CP_COMMIT();
        g1_chunk(2);

        cp_wait<0>(); __syncthreads();          // C3(e) ready; g1(2) closed
        if (e + 1 < BOND) { stage_chunk(e + 1, 0); CP_COMMIT(); }
        g1_chunk(3);

        // ---- X1 -> smem, pre-rounded tf32 (A operand of GEMM2) ----
        #pragma unroll
        for (int mt = 0; mt < 2; mt++) {
            #pragma unroll
            for (int nt = 0; nt < 4; nt++) {
                const int row = m0 + mt * 16 + r4;
                const int col = d0 + nt * 8 + 2 * c4;
                *reinterpret_cast<float2*>(sX1 + row * P_X1 + col) =
                    make_float2(f2tf32f(acc1[mt][nt][0]), f2tf32f(acc1[mt][nt][1]));
                *reinterpret_cast<float2*>(sX1 + (row + 8) * P_X1 + col) =
                    make_float2(f2tf32f(acc1[mt][nt][2]), f2tf32f(acc1[mt][nt][3]));
            }
        }
        __syncthreads();   // X1 visible; g1(3) closed
        if (e + 1 < BOND) { stage_chunk(e + 1, 1); CP_COMMIT(); }

        // ---- GEMM2: OUT[m,u] += sum_d X1[m,d]*K[d,u]; warp tile 32x64 ----
        #pragma unroll 2
        for (int ks = 0; ks < 8; ks++) {
            const int kk = ks * 8;
            uint32_t a[2][4];
            #pragma unroll
            for (int mt = 0; mt < 2; mt++) {
                const float* pa = sX1 + (m0 + mt * 16 + r4) * P_X1 + kk + c4;
                a[mt][0] = __float_as_uint(pa[0]);       // already tf32-rounded
                a[mt][1] = __float_as_uint(pa[8 * P_X1]);
                a[mt][2] = __float_as_uint(pa[4]);
                a[mt][3] = __float_as_uint(pa[8 * P_X1 + 4]);
            }
            uint32_t bf[8][2];
            #pragma unroll
            for (int nt = 0; nt < 8; nt++) {
                const float* pb = sK + (kk + c4) * P_K + u0 + nt * 8 + r4;
                bf[nt][0] = __float_as_uint(f2tf32f(pb[0]));
                bf[nt][1] = __float_as_uint(f2tf32f(pb[4 * P_K]));
            }
            #pragma unroll
            for (int mt = 0; mt < 2; mt++)
                #pragma unroll
                for (int nt = 0; nt < 8; nt++)
                    mma_tf32(acc2[mt][nt], a[mt], bf[nt]);
        }
        // next bond's s0-bar orders sK/sX1/window reuse
    }

    // ---- epilogue: ReLU + store OUT[b][mh+m][u] ----
    float* ob = out + (size_t)b * (NDIM * UNITS) + (size_t)mh * UNITS;
    #pragma unroll
    for (int mt = 0; mt < 2; mt++) {
        #pragma unroll
        for (int nt = 0; nt < 8; nt++) {
            const int row = m0 + mt * 16 + r4;
            const int col = u0 + nt * 8 + 2 * c4;
            float2 v0 = make_float2(fmaxf(acc2[mt][nt][0], 0.0f), fmaxf(acc2[mt][nt][1], 0.0f));
            float2 v1 = make_float2(fmaxf(acc2[mt][nt][2], 0.0f), fmaxf(acc2[mt][nt][3], 0.0f));
            *reinterpret_cast<float2*>(ob + row * UNITS + col)       = v0;
            *reinterpret_cast<float2*>(ob + (row + 8) * UNITS + col) = v1;
        }
    }
}

extern "C" void kernel_launch(void* const* d_in, const int* in_sizes, int n_in,
                              void* d_out, int out_size) {
    const float* adj  = nullptr;
    const float* feat = nullptr;
    const float* ker  = nullptr;
    for (int i = 0; i < n_in; i++) {
        if      (in_sizes[i] == BSZ * BOND * NDIM * NDIM)  adj  = (const float*)d_in[i];
        else if (in_sizes[i] == BSZ * NDIM * ATOM)         feat = (const float*)d_in[i];
        else if (in_sizes[i] == BSZ * BOND * ATOM * UNITS) ker  = (const float*)d_in[i];
    }
    if (!adj)  adj  = (const float*)d_in[0];
    if (!feat) feat = (const float*)d_in[1];
    if (!ker)  ker  = (const float*)d_in[2];

    cudaFuncSetAttribute(rgc_kernel, cudaFuncAttributeMaxDynamicSharedMemorySize, SMEM_BYTES);
    rgc_kernel<<<BSZ * 2, THREADS, SMEM_BYTES>>>(adj, feat, ker, (float*)d_out);
}

// round 12
// speedup vs baseline: 1.0914x; 1.0914x over previous
#include <cuda_runtime.h>
#include <cstdint>

#define BSZ    256
#define BOND   5
#define NDIM   128
#define ATOM   64
#define UNITS  128
#define THREADS 256

// smem float-word pitches (conflict-free fragment access; pitch % 32 == 4 or 8)
#define P_F    72    // F    [n=128][d=64]  (pre-rounded tf32, shared by both halves)
#define P_ADJ  132   // adjH [m=64][n=128]  per-half
#define P_K    136   // K_H  [d=64][u=128]  per-half copy
#define P_X1   68    // X1_H [m=64][d=64]   per-half

// smem layout in float words: F | adjH0 | adjH1 | K_H0 | K_H1 | X1_H0 | X1_H1
#define OFF_F    0
#define OFF_ADJ  (OFF_F   + NDIM * P_F)          // 9216
#define ADJ_H    (64 * P_ADJ)                    // 8448 per half
#define OFF_K    (OFF_ADJ + 2 * ADJ_H)           // 26112
#define K_H      (ATOM * P_K)                    // 8704 per half
#define OFF_X1   (OFF_K + 2 * K_H)               // 43520
#define X1_H     (64 * P_X1)                     // 4352 per half
#define SMEM_WORDS (OFF_X1 + 2 * X1_H)           // 52224
#define SMEM_BYTES (SMEM_WORDS * 4)              // 208896 (< 227KB)

__device__ __forceinline__ float f2tf32f(float f) {
    uint32_t u;
    asm("cvt.rna.tf32.f32 %0, %1;" : "=r"(u) : "f"(f));
    return __uint_as_float(u);
}

__device__ __forceinline__ void mma_tf32(float c[4], const uint32_t a[4], const uint32_t b[2]) {
    asm volatile(
        "mma.sync.aligned.m16n8k8.row.col.f32.tf32.tf32.f32 "
        "{%0,%1,%2,%3}, {%4,%5,%6,%7}, {%8,%9}, {%0,%1,%2,%3};"
        : "+f"(c[0]), "+f"(c[1]), "+f"(c[2]), "+f"(c[3])
        : "r"(a[0]), "r"(a[1]), "r"(a[2]), "r"(a[3]), "r"(b[0]), "r"(b[1]));
}

__device__ __forceinline__ uint32_t smem_u32(const void* p) {
    uint32_t a;
    asm("{ .reg .u64 t; cvta.to.shared.u64 t, %1; cvt.u32.u64 %0, t; }" : "=r"(a) : "l"(p));
    return a;
}
__device__ __forceinline__ void cpa16(uint32_t s, const float4* g) {
    asm volatile("cp.async.cg.shared.global [%0], [%1], 16;" :: "r"(s), "l"(g) : "memory");
}
#define CP_COMMIT() asm volatile("cp.async.commit_group;" ::: "memory")
template<int N> __device__ __forceinline__ void cp_wait() {
    asm volatile("cp.async.wait_group %0;" :: "n"(N) : "memory");
}
// half-CTA barrier: id 1 for half 0 (warps 0-3), id 2 for half 1 (warps 4-7)
__device__ __forceinline__ void hbar(int h) {
    asm volatile("bar.sync %0, 128;" :: "r"(h + 1) : "memory");
}

__global__ void __launch_bounds__(THREADS, 1)
rgc_kernel(const float* __restrict__ adjacency,
           const float* __restrict__ features,
           const float* __restrict__ kern,
           float* __restrict__ out) {
    extern __shared__ float sm[];
    const int tid = threadIdx.x;
    const int h   = tid >> 7;          // half index (0/1): warps 0-3 | 4-7
    const int ht  = tid & 127;         // thread id within half
    const int lw  = ht >> 5;           // local warp 0-3
    const int lid = tid & 31;
    const int r4  = lid >> 2;
    const int c4  = lid & 3;
    const int b   = blockIdx.x;
    const int mh  = h << 6;            // global m base of this half

    float* sF   = sm + OFF_F;
    float* sAdj = sm + OFF_ADJ + h * ADJ_H;   // this half's adjacency rows
    float* sK   = sm + OFF_K   + h * K_H;     // this half's K copy
    float* sX1  = sm + OFF_X1  + h * X1_H;    // this half's X1

    const uint32_t smb   = smem_u32(sm);
    const uint32_t sAdjB = smb + (OFF_ADJ + h * ADJ_H) * 4u;
    const uint32_t sKB   = smb + (OFF_K   + h * K_H)   * 4u;

    // per-half warp tiling, identical shapes to champion:
    const int m0 = (lw & 1) * 32;      // local M tile base (within 64-row half)
    const int d0 = (lw >> 1) * 32;     // GEMM1 N (=atom) tile base
    const int u0 = (lw >> 1) * 64;     // GEMM2 N (=units) tile base

    const float4* adjB  = reinterpret_cast<const float4*>(adjacency) + (size_t)(b * BOND) * 4096;
    const float4* kerB  = reinterpret_cast<const float4*>(kern)      + (size_t)(b * BOND) * 2048;
    const float4* featB = reinterpret_cast<const float4*>(features)  + (size_t)b * 2048;

    // stage this half's 64 rows of adjacency col-chunk c (512 float4, 4/thread)
    auto stage_adj_chunk = [&](int e, int c) {
        const float4* src = adjB + (size_t)e * 4096;
        #pragma unroll
        for (int t = 0; t < 4; t++) {
            int i = ht + t * 128;               // 0..511
            int m = i >> 3, j = i & 7;
            cpa16(sAdjB + (uint32_t)(m * P_ADJ + (c * 8 + j) * 4) * 4u,
                  src + (mh + m) * 32 + c * 8 + j);
        }
    };
    // stage this half's private K copy (2048 float4, 16/thread)
    auto stage_K = [&](int e) {
        const float4* src = kerB + (size_t)e * 2048;
        #pragma unroll
        for (int t = 0; t < 16; t++) {
            int i = ht + t * 128;               // 0..2047
            int dd = i >> 5, u4 = i & 31;
            cpa16(sKB + (uint32_t)(dd * P_K + u4 * 4) * 4u, src + i);
        }
    };
    // commit the 5 FIFO groups for bond e: {C0},{C1},{C2},{C3},{K}
    auto commit_bond = [&](int e) {
        stage_adj_chunk(e, 0); CP_COMMIT();
        stage_adj_chunk(e, 1); CP_COMMIT();
        stage_adj_chunk(e, 2); CP_COMMIT();
        stage_adj_chunk(e, 3); CP_COMMIT();
        stage_K(e);            CP_COMMIT();
    };

    // ---- prologue: F (full CTA, pre-rounded), full sync, then per-half bond-0 groups ----
    {
        #pragma unroll
        for (int t = 0; t < 8; t++) {
            int i = tid + t * THREADS;          // 0..2047
            float4 v = featB[i];
            int node = i >> 4, a4 = i & 15;
            float* d = sF + node * P_F + a4 * 4;
            d[0] = f2tf32f(v.x); d[1] = f2tf32f(v.y);
            d[2] = f2tf32f(v.z); d[3] = f2tf32f(v.w);
        }
        __syncthreads();                        // F visible to both halves
        commit_bond(0);
    }

    float acc2[2][8][4];
    #pragma unroll
    for (int mt = 0; mt < 2; mt++)
        #pragma unroll
        for (int nt = 0; nt < 8; nt++)
            #pragma unroll
            for (int k = 0; k < 4; k++) acc2[mt][nt][k] = 0.0f;

    float acc1[2][4][4];

    auto load_g1 = [&](int c, int ks, uint32_t (&a)[2][4], uint32_t (&bf)[4][2]) {
        const int k0 = c * 32 + ks * 8;
        #pragma unroll
        for (int mt = 0; mt < 2; mt++) {
            const float* pa = sAdj + (m0 + mt * 16 + r4) * P_ADJ + k0 + c4;
            a[mt][0] = __float_as_uint(pa[0]);           // raw fp32 (HW tf32 trunc)
            a[mt][1] = __float_as_uint(pa[8 * P_ADJ]);
            a[mt][2] = __float_as_uint(pa[4]);
            a[mt][3] = __float_as_uint(pa[8 * P_ADJ + 4]);
        }
        #pragma unroll
        for (int nt = 0; nt < 4; nt++) {
            const float* pb = sF + (k0 + c4) * P_F + d0 + nt * 8 + r4;
            bf[nt][0] = __float_as_uint(pb[0]);          // pre-rounded at staging
            bf[nt][1] = __float_as_uint(pb[4 * P_F]);
        }
    };
    auto g1_chunk = [&](int c) {                 // R8-style fragment double-buffer
        uint32_t a[2][2][4], bf[2][4][2];
        load_g1(c, 0, a[0], bf[0]);
        #pragma unroll
        for (int ks = 0; ks < 4; ks++) {
            if (ks < 3) load_g1(c, ks + 1, a[(ks + 1) & 1], bf[(ks + 1) & 1]);
            #pragma unroll
            for (int mt = 0; mt < 2; mt++)
                #pragma unroll
                for (int nt = 0; nt < 4; nt++)
                    mma_tf32(acc1[mt][nt], a[ks & 1][mt], bf[ks & 1][nt]);
        }
    };

    // FIFO per half, per bond (flight at bond entry = {C0,C1,C2,C3,K}):
    //  s0: wait<4>|hbar| g1(0)      s1: wait<3>|hbar| g1(1)
    //  s2: wait<2>|hbar| g1(2)      s3: wait<1>|hbar| g1(3)
    //  X1: store, wait<0> (K landed), hbar, commit {C0'..C3'} (adj dead)
    //  G2(e) reads K+X1; hbar; commit {K'} (K dead) -> next bond entry flight = 5
    #pragma unroll 1
    for (int e = 0; e < BOND; e++) {
        #pragma unroll
        for (int mt = 0; mt < 2; mt++)
            #pragma unroll
            for (int nt = 0; nt < 4; nt++)
                #pragma unroll
                for (int k = 0; k < 4; k++) acc1[mt][nt][k] = 0.0f;

        cp_wait<4>(); hbar(h); g1_chunk(0);
        cp_wait<3>(); hbar(h); g1_chunk(1);
        cp_wait<2>(); hbar(h); g1_chunk(2);
        cp_wait<1>(); hbar(h); g1_chunk(3);

        // ---- X1 -> smem, pre-rounded tf32 (A operand of GEMM2) ----
        #pragma unroll
        for (int mt = 0; mt < 2; mt++) {
            #pragma unroll
            for (int nt = 0; nt < 4; nt++) {
                const int row = m0 + mt * 16 + r4;
                const int col = d0 + nt * 8 + 2 * c4;
                *reinterpret_cast<float2*>(sX1 + row * P_X1 + col) =
                    make_float2(f2tf32f(acc1[mt][nt][0]), f2tf32f(acc1[mt][nt][1]));
                *reinterpret_cast<float2*>(sX1 + (row + 8) * P_X1 + col) =
                    make_float2(f2tf32f(acc1[mt][nt][2]), f2tf32f(acc1[mt][nt][3]));
            }
        }
        cp_wait<0>();        // K(e) landed
        hbar(h);             // X1 visible in half; adj reads closed
        if (e + 1 < BOND) {
            stage_adj_chunk(e + 1, 0); CP_COMMIT();
            stage_adj_chunk(e + 1, 1); CP_COMMIT();
            stage_adj_chunk(e + 1, 2); CP_COMMIT();
            stage_adj_chunk(e + 1, 3); CP_COMMIT();
        }

        // ---- GEMM2: OUT[m,u] += sum_d X1[m,d]*K[d,u]; warp tile 32x64, pipelined ----
        auto load_g2 = [&](int ks, uint32_t (&a)[2][4], uint32_t (&bf)[8][2]) {
            const int k0 = ks * 8;
            #pragma unroll
            for (int mt = 0; mt < 2; mt++) {
                const float* pa = sX1 + (m0 + mt * 16 + r4) * P_X1 + k0 + c4;
                a[mt][0] = __float_as_uint(pa[0]);       // already tf32-rounded
                a[mt][1] = __float_as_uint(pa[8 * P_X1]);
                a[mt][2] = __float_as_uint(pa[4]);
                a[mt][3] = __float_as_uint(pa[8 * P_X1 + 4]);
            }
            #pragma unroll
            for (int nt = 0; nt < 8; nt++) {
                const float* pb = sK + (k0 + c4) * P_K + u0 + nt * 8 + r4;
                bf[nt][0] = __float_as_uint(f2tf32f(pb[0]));
                bf[nt][1] = __float_as_uint(f2tf32f(pb[4 * P_K]));
            }
        };
        {
            uint32_t a[2][2][4], bf[2][8][2];
            load_g2(0, a[0], bf[0]);
            #pragma unroll
            for (int ks = 0; ks < 8; ks++) {
                if (ks < 7) load_g2(ks + 1, a[(ks + 1) & 1], bf[(ks + 1) & 1]);
                #pragma unroll
                for (int mt = 0; mt < 2; mt++)
                    #pragma unroll
                    for (int nt = 0; nt < 8; nt++)
                        mma_tf32(acc2[mt][nt], a[ks & 1][mt], bf[ks & 1][nt]);
            }
        }
        hbar(h);             // all half-warps done reading K before K' commit
        if (e + 1 < BOND) { stage_K(e + 1); CP_COMMIT(); }
    }

    // ---- epilogue: ReLU + store OUT[b][mh+m][u] ----
    float* ob = out + (size_t)b * (NDIM * UNITS) + (size_t)mh * UNITS;
    #pragma unroll
    for (int mt = 0; mt < 2; mt++) {
        #pragma unroll
        for (int nt = 0; nt < 8; nt++) {
            const int row = m0 + mt * 16 + r4;
            const int col = u0 + nt * 8 + 2 * c4;
            float2 v0 = make_float2(fmaxf(acc2[mt][nt][0], 0.0f), fmaxf(acc2[mt][nt][1], 0.0f));
            float2 v1 = make_float2(fmaxf(acc2[mt][nt][2], 0.0f), fmaxf(acc2[mt][nt][3], 0.0f));
            *reinterpret_cast<float2*>(ob + row * UNITS + col)       = v0;
            *reinterpret_cast<float2*>(ob + (row + 8) * UNITS + col) = v1;
        }
    }
}

extern "C" void kernel_launch(void* const* d_in, const int* in_sizes, int n_in,
                              void* d_out, int out_size) {
    const float* adj  = nullptr;
    const float* feat = nullptr;
    const float* ker  = nullptr;
    for (int i = 0; i < n_in; i++) {
        if      (in_sizes[i] == BSZ * BOND * NDIM * NDIM)  adj  = (const float*)d_in[i];
        else if (in_sizes[i] == BSZ * NDIM * ATOM)         feat = (const float*)d_in[i];
        else if (in_sizes[i] == BSZ * BOND * ATOM * UNITS) ker  = (const float*)d_in[i];
    }
    if (!adj)  adj  = (const float*)d_in[0];
    if (!feat) feat = (const float*)d_in[1];
    if (!ker)  ker  = (const float*)d_in[2];

    cudaFuncSetAttribute(rgc_kernel, cudaFuncAttributeMaxDynamicSharedMemorySize, SMEM_BYTES);
    rgc_kernel<<<BSZ, THREADS, SMEM_BYTES>>>(adj, feat, ker, (float*)d_out);
}